// round 16
// baseline (speedup 1.0000x reference)
#include <cuda_runtime.h>
#include <math.h>
#include <stdint.h>

#define BATCH 8
#define NPTS1 1024
#define NPTS2 4096
#define CH1 256
#define CH2 128
#define CHS 64
#define CTOT 448
#define HDIM 256
#define MROWS (BATCH * NPTS2)   // 32768

__device__ __forceinline__ uint32_t tf32b(float x) {
    unsigned u;
    asm("cvt.rna.tf32.f32 %0, %1;" : "=r"(u) : "f"(x));
    return u;
}

__device__ __forceinline__ void mma8(float* c, const uint32_t* a, const uint32_t* b) {
    asm volatile("mma.sync.aligned.m16n8k8.row.col.f32.tf32.tf32.f32 "
                 "{%0,%1,%2,%3}, {%4,%5,%6,%7}, {%8,%9}, {%0,%1,%2,%3};"
                 : "+f"(c[0]), "+f"(c[1]), "+f"(c[2]), "+f"(c[3])
                 : "r"(a[0]), "r"(a[1]), "r"(a[2]), "r"(a[3]), "r"(b[0]), "r"(b[1]));
}

// ---------------- scratch (device globals; no allocation) ----------------
__device__ float g_f1t[BATCH * NPTS1 * CH1];
__device__ float g_x[MROWS * CTOT];
__device__ float g_y1[MROWS * HDIM];
__device__ float g_y2[MROWS * HDIM];
__device__ int   g_idx[MROWS * 3];
__device__ float g_w[MROWS * 3];
__device__ float g_part[2 * 256 * HDIM];
__device__ float g_scale1[HDIM], g_shift1[HDIM];
__device__ float g_scale2[HDIM], g_shift2[HDIM];

// ---------------- transpose features1 [B, C1, N1] -> [B, N1, C1] ----------------
__global__ void transpose_f1(const float* __restrict__ in, float* __restrict__ out)
{
    __shared__ float tile[32][33];
    int b = blockIdx.z;
    int n0 = blockIdx.x * 32, c0 = blockIdx.y * 32;
    int tx = threadIdx.x, ty = threadIdx.y;
    const float* inb = in + (size_t)b * CH1 * NPTS1;
    #pragma unroll
    for (int i = 0; i < 32; i += 8)
        tile[ty + i][tx] = inb[(size_t)(c0 + ty + i) * NPTS1 + n0 + tx];
    __syncthreads();
    #pragma unroll
    for (int i = 0; i < 32; i += 8) {
        int n = n0 + ty + i;
        out[((size_t)b * NPTS1 + n) * CH1 + c0 + tx] = tile[tx][ty + i];
    }
}

// ---------------- merged transpose: features2 + skip -> g_x columns 256..447 ----
__global__ void transpose_f2s(const float* __restrict__ f2, const float* __restrict__ sk,
                              float* __restrict__ out)
{
    __shared__ float tile[32][33];
    int b = blockIdx.z;
    int yt = blockIdx.y;
    const float* in; int Cin, c0, colOff;
    if (yt < 4) { in = f2; Cin = CH2; c0 = yt * 32;      colOff = CH1; }
    else        { in = sk; Cin = CHS; c0 = (yt - 4) * 32; colOff = CH1 + CH2; }
    int n0 = blockIdx.x * 32;
    int tx = threadIdx.x, ty = threadIdx.y;
    const float* inb = in + (size_t)b * Cin * NPTS2;
    #pragma unroll
    for (int i = 0; i < 32; i += 8)
        tile[ty + i][tx] = inb[(size_t)(c0 + ty + i) * NPTS2 + n0 + tx];
    __syncthreads();
    #pragma unroll
    for (int i = 0; i < 32; i += 8) {
        int n = n0 + ty + i;
        out[((size_t)b * NPTS2 + n) * CTOT + colOff + c0 + tx] = tile[tx][ty + i];
    }
}

// ---------------- 3-NN: 8 lanes/query, d^2 ranking (top-4) + final sqrt re-rank ----
// Scan ranks by squared distance (no sqrt in loop). sqrt is monotone, so top-3 by
// (sqrt d2, idx) is contained in top-4 by (d2, idx) unless >=2 sqrt-compression tie
// inversions stack at the list boundary (measure-zero). Final: 4 sqrts, stable
// re-sort by (d, idx) == lax.top_k semantics, take 3.
__global__ void knn_kernel(const float* __restrict__ p1, const float* __restrict__ p2)
{
    __shared__ float4 sp[8 * 129];
    const int b = blockIdx.y;
    const int tid = threadIdx.x;
    const int sub = tid & 7;
    const int n = blockIdx.x * 32 + (tid >> 3);

    const float* p1b = p1 + (size_t)b * 3 * NPTS1;
    for (int j = tid; j < NPTS1; j += 256) {
        float x = p1b[j], y = p1b[NPTS1 + j], z = p1b[2 * NPTS1 + j];
        float ssj = __fadd_rn(__fadd_rn(__fmul_rn(x, x), __fmul_rn(y, y)), __fmul_rn(z, z));
        sp[(j >> 7) * 129 + (j & 127)] = make_float4(2.f * x, 2.f * y, 2.f * z, ssj);
    }
    __syncthreads();

    const float* p2b = p2 + (size_t)b * 3 * NPTS2;
    const float qx = p2b[n], qy = p2b[NPTS2 + n], qz = p2b[2 * NPTS2 + n];
    const float s2 = __fadd_rn(__fadd_rn(__fmul_rn(qx, qx), __fmul_rn(qy, qy)),
                               __fmul_rn(qz, qz));

    float bd[4] = { 1e30f, 1e30f, 1e30f, 1e30f };
    int   bi[4] = { NPTS1, NPTS1, NPTS1, NPTS1 };

    const int j0 = sub * (NPTS1 / 8);
    const float4* slice = sp + sub * 129;
    #pragma unroll 4
    for (int jj = 0; jj < NPTS1 / 8; jj++) {
        float4 v = slice[jj];
        float dot2 = __fadd_rn(__fadd_rn(__fmul_rn(qx, v.x), __fmul_rn(qy, v.y)),
                               __fmul_rn(qz, v.z));
        float d2v = __fsub_rn(__fadd_rn(s2, v.w), dot2);
        // 4-deep insert by d2; ascending scan + strict < keeps lowest index on ties
        if (d2v < bd[3]) {
            int j = j0 + jj;
            if (d2v < bd[2]) {
                bd[3] = bd[2]; bi[3] = bi[2];
                if (d2v < bd[1]) {
                    bd[2] = bd[1]; bi[2] = bi[1];
                    if (d2v < bd[0]) {
                        bd[1] = bd[0]; bi[1] = bi[0]; bd[0] = d2v; bi[0] = j;
                    } else { bd[1] = d2v; bi[1] = j; }
                } else { bd[2] = d2v; bi[2] = j; }
            } else { bd[3] = d2v; bi[3] = j; }
        }
    }

    // merge 8 per-lane top-4 lists by lex (d2, idx)
    #pragma unroll
    for (int m = 1; m <= 4; m <<= 1) {
        float od[4]; int oi[4];
        #pragma unroll
        for (int t = 0; t < 4; t++) {
            od[t] = __shfl_xor_sync(0xFFFFFFFFu, bd[t], m);
            oi[t] = __shfl_xor_sync(0xFFFFFFFFu, bi[t], m);
        }
        #pragma unroll
        for (int t = 0; t < 4; t++) {
            float d = od[t]; int i = oi[t];
            if (d < bd[3] || (d == bd[3] && i < bi[3])) {
                if (d < bd[2] || (d == bd[2] && i < bi[2])) {
                    bd[3] = bd[2]; bi[3] = bi[2];
                    if (d < bd[1] || (d == bd[1] && i < bi[1])) {
                        bd[2] = bd[1]; bi[2] = bi[1];
                        if (d < bd[0] || (d == bd[0] && i < bi[0])) {
                            bd[1] = bd[0]; bi[1] = bi[0]; bd[0] = d; bi[0] = i;
                        } else { bd[1] = d; bi[1] = i; }
                    } else { bd[2] = d; bi[2] = i; }
                } else { bd[3] = d; bi[3] = i; }
            }
        }
    }

    if (sub == 0) {
        // 4 sqrts, then stable re-sort by (d, idx) to restore exact top_k order
        float dd[4]; int ii[4];
        #pragma unroll
        for (int t = 0; t < 4; t++) {
            dd[t] = sqrtf(fmaxf(bd[t], 0.f));
            ii[t] = bi[t];
        }
        #pragma unroll
        for (int p = 0; p < 3; p++)
            #pragma unroll
            for (int t = 0; t < 3 - p; t++) {
                bool swap = (dd[t + 1] < dd[t]) || (dd[t + 1] == dd[t] && ii[t + 1] < ii[t]);
                if (swap) {
                    float td = dd[t]; dd[t] = dd[t + 1]; dd[t + 1] = td;
                    int   ti = ii[t]; ii[t] = ii[t + 1]; ii[t + 1] = ti;
                }
            }
        float i0 = __fdiv_rn(1.f, __fadd_rn(dd[0], 1e-10f));
        float i1 = __fdiv_rn(1.f, __fadd_rn(dd[1], 1e-10f));
        float i2 = __fdiv_rn(1.f, __fadd_rn(dd[2], 1e-10f));
        float s = __fadd_rn(__fadd_rn(i0, i1), i2);
        size_t m = (size_t)b * NPTS2 + n;
        g_idx[m * 3 + 0] = ii[0]; g_idx[m * 3 + 1] = ii[1]; g_idx[m * 3 + 2] = ii[2];
        g_w[m * 3 + 0] = __fdiv_rn(i0, s);
        g_w[m * 3 + 1] = __fdiv_rn(i1, s);
        g_w[m * 3 + 2] = __fdiv_rn(i2, s);
    }
}

// ---------------- gather + interpolation into x[:, 0:256], float4 ----------------
__global__ void interp_kernel()
{
    const int t = threadIdx.x;
    const int lane64 = t & 63;
    const int rsub = t >> 6;
    const int m0 = blockIdx.x * 8;
    #pragma unroll
    for (int q = 0; q < 2; q++) {
        int m = m0 + q * 4 + rsub;
        int b = m >> 12;
        int i0 = g_idx[m * 3 + 0], i1 = g_idx[m * 3 + 1], i2 = g_idx[m * 3 + 2];
        float w0 = g_w[m * 3 + 0], w1 = g_w[m * 3 + 1], w2 = g_w[m * 3 + 2];
        const float4* f = (const float4*)(g_f1t + (size_t)b * NPTS1 * CH1);
        float4 a = f[(size_t)i0 * 64 + lane64];
        float4 c = f[(size_t)i1 * 64 + lane64];
        float4 e = f[(size_t)i2 * 64 + lane64];
        float4 v;
        v.x = w0 * a.x + w1 * c.x + w2 * e.x;
        v.y = w0 * a.y + w1 * c.y + w2 * e.y;
        v.z = w0 * a.z + w1 * c.z + w2 * e.z;
        v.w = w0 * a.w + w1 * c.w + w2 * e.w;
        *(float4*)(g_x + (size_t)m * CTOT + lane64 * 4) = v;
    }
}

// ---------------- mma.sync TF32 GEMM (static smem) + fused BN partial stats ----
template<int KD, bool BNRELU>
__global__ __launch_bounds__(256)
void mma_gemm(const float* __restrict__ A, const float* __restrict__ W,
              const float* __restrict__ bias,
              const float* __restrict__ scale, const float* __restrict__ shift,
              float* __restrict__ Y)
{
    constexpr int NC = KD / 32;
    __shared__ uint32_t As[128][36];
    __shared__ uint32_t Bs[128][36];
    __shared__ float sSc[BNRELU ? 256 : 1];
    __shared__ float sSh[BNRELU ? 256 : 1];
    __shared__ float sred[2][128][2];

    const int tid  = threadIdx.x;
    const int lane = tid & 31;
    const int wid  = tid >> 5;
    const int wm   = wid & 1;
    const int wn   = wid >> 1;
    const int m0   = blockIdx.x * 128;
    const int bn0  = blockIdx.y * 128;

    if (BNRELU) {
        sSc[tid] = scale[tid]; sSh[tid] = shift[tid];
        __syncthreads();
    }

    float c[4][4][4];
    #pragma unroll
    for (int i = 0; i < 4; i++)
        #pragma unroll
        for (int j = 0; j < 4; j++)
            #pragma unroll
            for (int r = 0; r < 4; r++) c[i][j][r] = 0.f;

    float4 ra[4], rb[4];

    auto loadAB = [&](int ck) {
        const int k0 = ck * 32;
        #pragma unroll
        for (int i = 0; i < 4; i++) {
            int f = tid + i * 256;
            int row = f >> 3, c4 = f & 7;
            ra[i] = *(const float4*)(A + (size_t)(m0 + row) * KD + k0 + c4 * 4);
            rb[i] = *(const float4*)(W + (size_t)(bn0 + row) * KD + k0 + c4 * 4);
        }
    };

    auto stsAB = [&](int ck) {
        const int k0 = ck * 32;
        #pragma unroll
        for (int i = 0; i < 4; i++) {
            int f = tid + i * 256;
            int row = f >> 3, c4 = f & 7;
            float4 v = ra[i];
            if (BNRELU) {
                int ch = k0 + c4 * 4;
                v.x = fmaxf(fmaf(v.x, sSc[ch + 0], sSh[ch + 0]), 0.f);
                v.y = fmaxf(fmaf(v.y, sSc[ch + 1], sSh[ch + 1]), 0.f);
                v.z = fmaxf(fmaf(v.z, sSc[ch + 2], sSh[ch + 2]), 0.f);
                v.w = fmaxf(fmaf(v.w, sSc[ch + 3], sSh[ch + 3]), 0.f);
            }
            As[row][c4 * 4 + 0] = tf32b(v.x);
            As[row][c4 * 4 + 1] = tf32b(v.y);
            As[row][c4 * 4 + 2] = tf32b(v.z);
            As[row][c4 * 4 + 3] = tf32b(v.w);
            float4 w4 = rb[i];
            Bs[row][c4 * 4 + 0] = tf32b(w4.x);
            Bs[row][c4 * 4 + 1] = tf32b(w4.y);
            Bs[row][c4 * 4 + 2] = tf32b(w4.z);
            Bs[row][c4 * 4 + 3] = tf32b(w4.w);
        }
    };

    loadAB(0);
    for (int ck = 0; ck < NC; ck++) {
        stsAB(ck);
        __syncthreads();
        if (ck + 1 < NC) loadAB(ck + 1);
        #pragma unroll
        for (int kk = 0; kk < 32; kk += 8) {
            uint32_t af[4][4], bf[4][2];
            const int kA = kk + (lane & 3);
            const int rA = (lane >> 2);
            #pragma unroll
            for (int mt = 0; mt < 4; mt++) {
                int mr = wm * 64 + mt * 16 + rA;
                af[mt][0] = As[mr][kA];
                af[mt][1] = As[mr + 8][kA];
                af[mt][2] = As[mr][kA + 4];
                af[mt][3] = As[mr + 8][kA + 4];
            }
            #pragma unroll
            for (int nt = 0; nt < 4; nt++) {
                int nr = wn * 32 + nt * 8 + rA;
                bf[nt][0] = Bs[nr][kA];
                bf[nt][1] = Bs[nr][kA + 4];
            }
            #pragma unroll
            for (int mt = 0; mt < 4; mt++)
                #pragma unroll
                for (int nt = 0; nt < 4; nt++)
                    mma8(c[mt][nt], af[mt], bf[nt]);
        }
        __syncthreads();
    }

    const int crow = lane >> 2;
    const int ccol = 2 * (lane & 3);
    #pragma unroll
    for (int nt = 0; nt < 4; nt++) {
        int col = bn0 + wn * 32 + nt * 8 + ccol;
        float bx = bias[col], by = bias[col + 1];
        #pragma unroll
        for (int mt = 0; mt < 4; mt++) {
            c[mt][nt][0] += bx; c[mt][nt][1] += by;
            c[mt][nt][2] += bx; c[mt][nt][3] += by;
            int r0 = m0 + wm * 64 + mt * 16 + crow;
            float2 v0 = { c[mt][nt][0], c[mt][nt][1] };
            float2 v1 = { c[mt][nt][2], c[mt][nt][3] };
            *(float2*)(Y + (size_t)r0 * 256 + col) = v0;
            *(float2*)(Y + (size_t)(r0 + 8) * 256 + col) = v1;
        }
    }

    #pragma unroll
    for (int nt = 0; nt < 4; nt++) {
        float s0 = 0.f, s1 = 0.f, q0 = 0.f, q1 = 0.f;
        #pragma unroll
        for (int mt = 0; mt < 4; mt++) {
            s0 += c[mt][nt][0] + c[mt][nt][2];
            s1 += c[mt][nt][1] + c[mt][nt][3];
            q0 += c[mt][nt][0] * c[mt][nt][0] + c[mt][nt][2] * c[mt][nt][2];
            q1 += c[mt][nt][1] * c[mt][nt][1] + c[mt][nt][3] * c[mt][nt][3];
        }
        #pragma unroll
        for (int m = 4; m <= 16; m <<= 1) {
            s0 += __shfl_xor_sync(0xFFFFFFFFu, s0, m);
            s1 += __shfl_xor_sync(0xFFFFFFFFu, s1, m);
            q0 += __shfl_xor_sync(0xFFFFFFFFu, q0, m);
            q1 += __shfl_xor_sync(0xFFFFFFFFu, q1, m);
        }
        if (lane < 4) {
            int cl = wn * 32 + nt * 8 + ccol;
            sred[wm][cl][0] = s0;     sred[wm][cl][1] = q0;
            sred[wm][cl + 1][0] = s1; sred[wm][cl + 1][1] = q1;
        }
    }
    __syncthreads();
    if (tid < 128) {
        float s = sred[0][tid][0] + sred[1][tid][0];
        float q = sred[0][tid][1] + sred[1][tid][1];
        g_part[blockIdx.x * HDIM + bn0 + tid] = s;
        g_part[256 * HDIM + blockIdx.x * HDIM + bn0 + tid] = q;
    }
}

// ---------------- parallel deterministic finalize: block per channel ----------------
__global__ void finalize_kernel(const float* __restrict__ g, const float* __restrict__ beta,
                                float* __restrict__ scale, float* __restrict__ shift)
{
    __shared__ float ss[256], sq[256];
    const int c = blockIdx.x;
    const int t = threadIdx.x;
    ss[t] = g_part[t * HDIM + c];
    sq[t] = g_part[256 * HDIM + t * HDIM + c];
    __syncthreads();
    #pragma unroll
    for (int st = 128; st > 0; st >>= 1) {
        if (t < st) { ss[t] += ss[t + st]; sq[t] += sq[t + st]; }
        __syncthreads();
    }
    if (t == 0) {
        const float invM = 1.f / (float)MROWS;
        float mu = ss[0] * invM;
        float var = sq[0] * invM - mu * mu;
        float sc = g[c] * rsqrtf(var + 1e-3f);
        scale[c] = sc;
        shift[c] = beta[c] - mu * sc;
    }
}

// ---------------- final BN+ReLU + transpose to [B, H, N2] ----------------
__global__ void output_kernel(float* __restrict__ out)
{
    __shared__ float tile[32][33];
    int b = blockIdx.z;
    int o0 = blockIdx.y * 32, n0 = blockIdx.x * 32;
    int tx = threadIdx.x, ty = threadIdx.y;
    float sc = g_scale2[o0 + tx], sh = g_shift2[o0 + tx];
    #pragma unroll
    for (int i = 0; i < 32; i += 8) {
        int n = n0 + ty + i;
        float v = g_y2[((size_t)b * NPTS2 + n) * HDIM + o0 + tx];
        tile[ty + i][tx] = fmaxf(fmaf(v, sc, sh), 0.f);
    }
    __syncthreads();
    #pragma unroll
    for (int i = 0; i < 32; i += 8) {
        int o = o0 + ty + i;
        out[((size_t)b * HDIM + o) * NPTS2 + n0 + tx] = tile[tx][ty + i];
    }
}

// ---------------- launch ----------------
extern "C" void kernel_launch(void* const* d_in, const int* in_sizes, int n_in,
                              void* d_out, int out_size)
{
    const float* points1   = (const float*)d_in[0];
    const float* points2   = (const float*)d_in[1];
    const float* features1 = (const float*)d_in[2];
    const float* features2 = (const float*)d_in[3];
    const float* skipf     = (const float*)d_in[4];
    const float* W1 = (const float*)d_in[5];
    const float* b1 = (const float*)d_in[6];
    const float* g1 = (const float*)d_in[7];
    const float* be1 = (const float*)d_in[8];
    const float* W2 = (const float*)d_in[9];
    const float* b2 = (const float*)d_in[10];
    const float* g2 = (const float*)d_in[11];
    const float* be2 = (const float*)d_in[12];
    float* out = (float*)d_out;

    void *p_f1t, *p_x, *p_y1, *p_y2, *p_sc1, *p_sh1, *p_sc2, *p_sh2;
    cudaGetSymbolAddress(&p_f1t, g_f1t);
    cudaGetSymbolAddress(&p_x,   g_x);
    cudaGetSymbolAddress(&p_y1,  g_y1);
    cudaGetSymbolAddress(&p_y2,  g_y2);
    cudaGetSymbolAddress(&p_sc1, g_scale1);
    cudaGetSymbolAddress(&p_sh1, g_shift1);
    cudaGetSymbolAddress(&p_sc2, g_scale2);
    cudaGetSymbolAddress(&p_sh2, g_shift2);

    dim3 tb(32, 8);

    transpose_f1<<<dim3(NPTS1 / 32, CH1 / 32, BATCH), tb>>>(features1, (float*)p_f1t);
    transpose_f2s<<<dim3(NPTS2 / 32, 6, BATCH), tb>>>(features2, skipf, (float*)p_x);
    knn_kernel<<<dim3(NPTS2 / 32, BATCH), 256>>>(points1, points2);
    interp_kernel<<<MROWS / 8, 256>>>();

    mma_gemm<CTOT, false><<<dim3(MROWS / 128, 2), 256>>>(
        (const float*)p_x, W1, b1, nullptr, nullptr, (float*)p_y1);
    finalize_kernel<<<256, 256>>>(g1, be1, (float*)p_sc1, (float*)p_sh1);

    mma_gemm<HDIM, true><<<dim3(MROWS / 128, 2), 256>>>(
        (const float*)p_y1, W2, b2,
        (const float*)p_sc1, (const float*)p_sh1, (float*)p_y2);
    finalize_kernel<<<256, 256>>>(g2, be2, (float*)p_sc2, (float*)p_sh2);

    output_kernel<<<dim3(NPTS2 / 32, HDIM / 32, BATCH), tb>>>(out);
}

// round 17
// speedup vs baseline: 1.0645x; 1.0645x over previous
#include <cuda_runtime.h>
#include <math.h>
#include <stdint.h>

#define BATCH 8
#define NPTS1 1024
#define NPTS2 4096
#define CH1 256
#define CH2 128
#define CHS 64
#define CTOT 448
#define HDIM 256
#define MROWS (BATCH * NPTS2)   // 32768

// GEMM dynamic smem layout (bytes): raw fp32 tiles, double buffered
#define SM_A0 0
#define SM_B0 18432
#define SM_A1 36864
#define SM_B1 55296
#define SM_SC 73728
#define SM_SH 74752
#define SM_RED 75776
#define SM_TOT 77824

__device__ __forceinline__ uint32_t tf32b(float x) {
    unsigned u;
    asm("cvt.rna.tf32.f32 %0, %1;" : "=r"(u) : "f"(x));
    return u;
}

__device__ __forceinline__ void mma8(float* c, const uint32_t* a, const uint32_t* b) {
    asm volatile("mma.sync.aligned.m16n8k8.row.col.f32.tf32.tf32.f32 "
                 "{%0,%1,%2,%3}, {%4,%5,%6,%7}, {%8,%9}, {%0,%1,%2,%3};"
                 : "+f"(c[0]), "+f"(c[1]), "+f"(c[2]), "+f"(c[3])
                 : "r"(a[0]), "r"(a[1]), "r"(a[2]), "r"(a[3]), "r"(b[0]), "r"(b[1]));
}

// ---------------- scratch (device globals; no allocation) ----------------
__device__ float g_f1t[BATCH * NPTS1 * CH1];
__device__ float g_x[MROWS * CTOT];
__device__ float g_y1[MROWS * HDIM];
__device__ float g_y2[MROWS * HDIM];
__device__ int   g_idx[MROWS * 3];
__device__ float g_w[MROWS * 3];
__device__ float g_part[2 * 256 * HDIM];
__device__ float g_scale1[HDIM], g_shift1[HDIM];
__device__ float g_scale2[HDIM], g_shift2[HDIM];

// ---------------- transpose features1 [B, C1, N1] -> [B, N1, C1] ----------------
__global__ void transpose_f1(const float* __restrict__ in, float* __restrict__ out)
{
    __shared__ float tile[32][33];
    int b = blockIdx.z;
    int n0 = blockIdx.x * 32, c0 = blockIdx.y * 32;
    int tx = threadIdx.x, ty = threadIdx.y;
    const float* inb = in + (size_t)b * CH1 * NPTS1;
    #pragma unroll
    for (int i = 0; i < 32; i += 8)
        tile[ty + i][tx] = inb[(size_t)(c0 + ty + i) * NPTS1 + n0 + tx];
    __syncthreads();
    #pragma unroll
    for (int i = 0; i < 32; i += 8) {
        int n = n0 + ty + i;
        out[((size_t)b * NPTS1 + n) * CH1 + c0 + tx] = tile[tx][ty + i];
    }
}

// ---------------- merged transpose: features2 + skip -> g_x columns 256..447 ----
__global__ void transpose_f2s(const float* __restrict__ f2, const float* __restrict__ sk,
                              float* __restrict__ out)
{
    __shared__ float tile[32][33];
    int b = blockIdx.z;
    int yt = blockIdx.y;
    const float* in; int Cin, c0, colOff;
    if (yt < 4) { in = f2; Cin = CH2; c0 = yt * 32;      colOff = CH1; }
    else        { in = sk; Cin = CHS; c0 = (yt - 4) * 32; colOff = CH1 + CH2; }
    int n0 = blockIdx.x * 32;
    int tx = threadIdx.x, ty = threadIdx.y;
    const float* inb = in + (size_t)b * Cin * NPTS2;
    #pragma unroll
    for (int i = 0; i < 32; i += 8)
        tile[ty + i][tx] = inb[(size_t)(c0 + ty + i) * NPTS2 + n0 + tx];
    __syncthreads();
    #pragma unroll
    for (int i = 0; i < 32; i += 8) {
        int n = n0 + ty + i;
        out[((size_t)b * NPTS2 + n) * CTOT + colOff + c0 + tx] = tile[tx][ty + i];
    }
}

// ---------------- 3-NN: 8 lanes/query, (2x,2y,2z,ss) candidates (R15 form) ----------------
__global__ void knn_kernel(const float* __restrict__ p1, const float* __restrict__ p2)
{
    __shared__ float4 sp[8 * 129];
    const int b = blockIdx.y;
    const int tid = threadIdx.x;
    const int sub = tid & 7;
    const int n = blockIdx.x * 32 + (tid >> 3);

    const float* p1b = p1 + (size_t)b * 3 * NPTS1;
    for (int j = tid; j < NPTS1; j += 256) {
        float x = p1b[j], y = p1b[NPTS1 + j], z = p1b[2 * NPTS1 + j];
        float ssj = __fadd_rn(__fadd_rn(__fmul_rn(x, x), __fmul_rn(y, y)), __fmul_rn(z, z));
        sp[(j >> 7) * 129 + (j & 127)] = make_float4(2.f * x, 2.f * y, 2.f * z, ssj);
    }
    __syncthreads();

    const float* p2b = p2 + (size_t)b * 3 * NPTS2;
    const float qx = p2b[n], qy = p2b[NPTS2 + n], qz = p2b[2 * NPTS2 + n];
    const float s2 = __fadd_rn(__fadd_rn(__fmul_rn(qx, qx), __fmul_rn(qy, qy)),
                               __fmul_rn(qz, qz));

    float bd0 = 1e30f, bd1 = 1e30f, bd2 = 1e30f;
    int bi0 = NPTS1, bi1 = NPTS1, bi2 = NPTS1;

    const int j0 = sub * (NPTS1 / 8);
    const float4* slice = sp + sub * 129;
    #pragma unroll 4
    for (int jj = 0; jj < NPTS1 / 8; jj++) {
        float4 v = slice[jj];
        float dot2 = __fadd_rn(__fadd_rn(__fmul_rn(qx, v.x), __fmul_rn(qy, v.y)),
                               __fmul_rn(qz, v.z));
        float d2v = __fsub_rn(__fadd_rn(s2, v.w), dot2);
        float d = sqrtf(fmaxf(d2v, 0.f));
        if (d < bd2) {
            int j = j0 + jj;
            if (d < bd1) {
                bd2 = bd1; bi2 = bi1;
                if (d < bd0) { bd1 = bd0; bi1 = bi0; bd0 = d; bi0 = j; }
                else         { bd1 = d;  bi1 = j; }
            } else { bd2 = d; bi2 = j; }
        }
    }

    #pragma unroll
    for (int m = 1; m <= 4; m <<= 1) {
        float od[3]; int oi[3];
        od[0] = __shfl_xor_sync(0xFFFFFFFFu, bd0, m);
        od[1] = __shfl_xor_sync(0xFFFFFFFFu, bd1, m);
        od[2] = __shfl_xor_sync(0xFFFFFFFFu, bd2, m);
        oi[0] = __shfl_xor_sync(0xFFFFFFFFu, bi0, m);
        oi[1] = __shfl_xor_sync(0xFFFFFFFFu, bi1, m);
        oi[2] = __shfl_xor_sync(0xFFFFFFFFu, bi2, m);
        #pragma unroll
        for (int t = 0; t < 3; t++) {
            float d = od[t]; int i = oi[t];
            if (d < bd2 || (d == bd2 && i < bi2)) {
                if (d < bd1 || (d == bd1 && i < bi1)) {
                    bd2 = bd1; bi2 = bi1;
                    if (d < bd0 || (d == bd0 && i < bi0)) {
                        bd1 = bd0; bi1 = bi0; bd0 = d; bi0 = i;
                    } else { bd1 = d; bi1 = i; }
                } else { bd2 = d; bi2 = i; }
            }
        }
    }

    if (sub == 0) {
        float i0 = __fdiv_rn(1.f, __fadd_rn(bd0, 1e-10f));
        float i1 = __fdiv_rn(1.f, __fadd_rn(bd1, 1e-10f));
        float i2 = __fdiv_rn(1.f, __fadd_rn(bd2, 1e-10f));
        float s = __fadd_rn(__fadd_rn(i0, i1), i2);
        size_t m = (size_t)b * NPTS2 + n;
        g_idx[m * 3 + 0] = bi0; g_idx[m * 3 + 1] = bi1; g_idx[m * 3 + 2] = bi2;
        g_w[m * 3 + 0] = __fdiv_rn(i0, s);
        g_w[m * 3 + 1] = __fdiv_rn(i1, s);
        g_w[m * 3 + 2] = __fdiv_rn(i2, s);
    }
}

// ---------------- gather + interpolation into x[:, 0:256], float4 ----------------
__global__ void interp_kernel()
{
    const int t = threadIdx.x;
    const int lane64 = t & 63;
    const int rsub = t >> 6;
    const int m0 = blockIdx.x * 8;
    #pragma unroll
    for (int q = 0; q < 2; q++) {
        int m = m0 + q * 4 + rsub;
        int b = m >> 12;
        int i0 = g_idx[m * 3 + 0], i1 = g_idx[m * 3 + 1], i2 = g_idx[m * 3 + 2];
        float w0 = g_w[m * 3 + 0], w1 = g_w[m * 3 + 1], w2 = g_w[m * 3 + 2];
        const float4* f = (const float4*)(g_f1t + (size_t)b * NPTS1 * CH1);
        float4 a = f[(size_t)i0 * 64 + lane64];
        float4 c = f[(size_t)i1 * 64 + lane64];
        float4 e = f[(size_t)i2 * 64 + lane64];
        float4 v;
        v.x = w0 * a.x + w1 * c.x + w2 * e.x;
        v.y = w0 * a.y + w1 * c.y + w2 * e.y;
        v.z = w0 * a.z + w1 * c.z + w2 * e.z;
        v.w = w0 * a.w + w1 * c.w + w2 * e.w;
        *(float4*)(g_x + (size_t)m * CTOT + lane64 * 4) = v;
    }
}

// ---------------- mma.sync TF32 GEMM: cp.async double-buffer, cvt at fragment load ----
template<int KD, bool BNRELU>
__global__ __launch_bounds__(256)
void mma_gemm(const float* __restrict__ A, const float* __restrict__ W,
              const float* __restrict__ bias,
              const float* __restrict__ scale, const float* __restrict__ shift,
              float* __restrict__ Y)
{
    constexpr int NC = KD / 32;
    extern __shared__ __align__(16) char dsm[];
    float* sSc = (float*)(dsm + SM_SC);
    float* sSh = (float*)(dsm + SM_SH);
    float (*sred)[128][2] = (float(*)[128][2])(dsm + SM_RED);
    const uint32_t sb = (uint32_t)__cvta_generic_to_shared(dsm);

    const int tid  = threadIdx.x;
    const int lane = tid & 31;
    const int wid  = tid >> 5;
    const int wm   = wid & 1;
    const int wn   = wid >> 1;
    const int m0   = blockIdx.x * 128;
    const int bn0  = blockIdx.y * 128;

    if (BNRELU) { sSc[tid] = scale[tid]; sSh[tid] = shift[tid]; }
    // ordered before first use by the first mainloop __syncthreads()

    // staging indices: f = tid + i*256 over 1024 float4; row = f>>3, c4 = f&7
    const int srow = tid >> 3, sc4 = tid & 7;

    auto issue = [&](int ck, int buf) {
        const int k0 = ck * 32;
        const uint32_t abase = sb + (buf ? SM_A1 : SM_A0);
        const uint32_t bbase = sb + (buf ? SM_B1 : SM_B0);
        #pragma unroll
        for (int i = 0; i < 4; i++) {
            int row = srow + i * 32;
            uint32_t off = (uint32_t)(row * 36 + sc4 * 4) * 4;
            const float* ga = A + (size_t)(m0 + row) * KD + k0 + sc4 * 4;
            asm volatile("cp.async.ca.shared.global [%0], [%1], 16;"
                         :: "r"(abase + off), "l"(ga));
            const float* gb = W + (size_t)(bn0 + row) * KD + k0 + sc4 * 4;
            asm volatile("cp.async.ca.shared.global [%0], [%1], 16;"
                         :: "r"(bbase + off), "l"(gb));
        }
        asm volatile("cp.async.commit_group;" ::: "memory");
    };

    float c[4][4][4];
    #pragma unroll
    for (int i = 0; i < 4; i++)
        #pragma unroll
        for (int j = 0; j < 4; j++)
            #pragma unroll
            for (int r = 0; r < 4; r++) c[i][j][r] = 0.f;

    issue(0, 0);

    for (int ck = 0; ck < NC; ck++) {
        const int cur = ck & 1;
        if (ck + 1 < NC) {
            issue(ck + 1, cur ^ 1);
            asm volatile("cp.async.wait_group 1;" ::: "memory");
        } else {
            asm volatile("cp.async.wait_group 0;" ::: "memory");
        }
        __syncthreads();
        const float (*As)[36] = (const float(*)[36])(dsm + (cur ? SM_A1 : SM_A0));
        const float (*Bs)[36] = (const float(*)[36])(dsm + (cur ? SM_B1 : SM_B0));
        const int k0 = ck * 32;
        #pragma unroll
        for (int kk = 0; kk < 32; kk += 8) {
            const int kA = kk + (lane & 3);
            const int rA = lane >> 2;
            float scA0, shA0, scA1, shA1;
            if (BNRELU) {
                scA0 = sSc[k0 + kA];     shA0 = sSh[k0 + kA];
                scA1 = sSc[k0 + kA + 4]; shA1 = sSh[k0 + kA + 4];
            }
            uint32_t af[4][4], bf[4][2];
            #pragma unroll
            for (int mt = 0; mt < 4; mt++) {
                int mr = wm * 64 + mt * 16 + rA;
                float a0 = As[mr][kA],     a1 = As[mr + 8][kA];
                float a2 = As[mr][kA + 4], a3 = As[mr + 8][kA + 4];
                if (BNRELU) {
                    a0 = fmaxf(fmaf(a0, scA0, shA0), 0.f);
                    a1 = fmaxf(fmaf(a1, scA0, shA0), 0.f);
                    a2 = fmaxf(fmaf(a2, scA1, shA1), 0.f);
                    a3 = fmaxf(fmaf(a3, scA1, shA1), 0.f);
                }
                af[mt][0] = tf32b(a0); af[mt][1] = tf32b(a1);
                af[mt][2] = tf32b(a2); af[mt][3] = tf32b(a3);
            }
            #pragma unroll
            for (int nt = 0; nt < 4; nt++) {
                int nr = wn * 32 + nt * 8 + rA;
                bf[nt][0] = tf32b(Bs[nr][kA]);
                bf[nt][1] = tf32b(Bs[nr][kA + 4]);
            }
            #pragma unroll
            for (int mt = 0; mt < 4; mt++)
                #pragma unroll
                for (int nt = 0; nt < 4; nt++)
                    mma8(c[mt][nt], af[mt], bf[nt]);
        }
        __syncthreads();
    }

    const int crow = lane >> 2;
    const int ccol = 2 * (lane & 3);
    #pragma unroll
    for (int nt = 0; nt < 4; nt++) {
        int col = bn0 + wn * 32 + nt * 8 + ccol;
        float bx = bias[col], by = bias[col + 1];
        #pragma unroll
        for (int mt = 0; mt < 4; mt++) {
            c[mt][nt][0] += bx; c[mt][nt][1] += by;
            c[mt][nt][2] += bx; c[mt][nt][3] += by;
            int r0 = m0 + wm * 64 + mt * 16 + crow;
            float2 v0 = { c[mt][nt][0], c[mt][nt][1] };
            float2 v1 = { c[mt][nt][2], c[mt][nt][3] };
            *(float2*)(Y + (size_t)r0 * 256 + col) = v0;
            *(float2*)(Y + (size_t)(r0 + 8) * 256 + col) = v1;
        }
    }

    #pragma unroll
    for (int nt = 0; nt < 4; nt++) {
        float s0 = 0.f, s1 = 0.f, q0 = 0.f, q1 = 0.f;
        #pragma unroll
        for (int mt = 0; mt < 4; mt++) {
            s0 += c[mt][nt][0] + c[mt][nt][2];
            s1 += c[mt][nt][1] + c[mt][nt][3];
            q0 += c[mt][nt][0] * c[mt][nt][0] + c[mt][nt][2] * c[mt][nt][2];
            q1 += c[mt][nt][1] * c[mt][nt][1] + c[mt][nt][3] * c[mt][nt][3];
        }
        #pragma unroll
        for (int m = 4; m <= 16; m <<= 1) {
            s0 += __shfl_xor_sync(0xFFFFFFFFu, s0, m);
            s1 += __shfl_xor_sync(0xFFFFFFFFu, s1, m);
            q0 += __shfl_xor_sync(0xFFFFFFFFu, q0, m);
            q1 += __shfl_xor_sync(0xFFFFFFFFu, q1, m);
        }
        if (lane < 4) {
            int cl = wn * 32 + nt * 8 + ccol;
            sred[wm][cl][0] = s0;     sred[wm][cl][1] = q0;
            sred[wm][cl + 1][0] = s1; sred[wm][cl + 1][1] = q1;
        }
    }
    __syncthreads();
    if (tid < 128) {
        float s = sred[0][tid][0] + sred[1][tid][0];
        float q = sred[0][tid][1] + sred[1][tid][1];
        g_part[blockIdx.x * HDIM + bn0 + tid] = s;
        g_part[256 * HDIM + blockIdx.x * HDIM + bn0 + tid] = q;
    }
}

// ---------------- parallel deterministic finalize: block per channel ----------------
__global__ void finalize_kernel(const float* __restrict__ g, const float* __restrict__ beta,
                                float* __restrict__ scale, float* __restrict__ shift)
{
    __shared__ float ss[256], sq[256];
    const int c = blockIdx.x;
    const int t = threadIdx.x;
    ss[t] = g_part[t * HDIM + c];
    sq[t] = g_part[256 * HDIM + t * HDIM + c];
    __syncthreads();
    #pragma unroll
    for (int st = 128; st > 0; st >>= 1) {
        if (t < st) { ss[t] += ss[t + st]; sq[t] += sq[t + st]; }
        __syncthreads();
    }
    if (t == 0) {
        const float invM = 1.f / (float)MROWS;
        float mu = ss[0] * invM;
        float var = sq[0] * invM - mu * mu;
        float sc = g[c] * rsqrtf(var + 1e-3f);
        scale[c] = sc;
        shift[c] = beta[c] - mu * sc;
    }
}

// ---------------- final BN+ReLU + transpose to [B, H, N2] ----------------
__global__ void output_kernel(float* __restrict__ out)
{
    __shared__ float tile[32][33];
    int b = blockIdx.z;
    int o0 = blockIdx.y * 32, n0 = blockIdx.x * 32;
    int tx = threadIdx.x, ty = threadIdx.y;
    float sc = g_scale2[o0 + tx], sh = g_shift2[o0 + tx];
    #pragma unroll
    for (int i = 0; i < 32; i += 8) {
        int n = n0 + ty + i;
        float v = g_y2[((size_t)b * NPTS2 + n) * HDIM + o0 + tx];
        tile[ty + i][tx] = fmaxf(fmaf(v, sc, sh), 0.f);
    }
    __syncthreads();
    #pragma unroll
    for (int i = 0; i < 32; i += 8) {
        int o = o0 + ty + i;
        out[((size_t)b * HDIM + o) * NPTS2 + n0 + tx] = tile[tx][ty + i];
    }
}

// ---------------- launch ----------------
extern "C" void kernel_launch(void* const* d_in, const int* in_sizes, int n_in,
                              void* d_out, int out_size)
{
    const float* points1   = (const float*)d_in[0];
    const float* points2   = (const float*)d_in[1];
    const float* features1 = (const float*)d_in[2];
    const float* features2 = (const float*)d_in[3];
    const float* skipf     = (const float*)d_in[4];
    const float* W1 = (const float*)d_in[5];
    const float* b1 = (const float*)d_in[6];
    const float* g1 = (const float*)d_in[7];
    const float* be1 = (const float*)d_in[8];
    const float* W2 = (const float*)d_in[9];
    const float* b2 = (const float*)d_in[10];
    const float* g2 = (const float*)d_in[11];
    const float* be2 = (const float*)d_in[12];
    float* out = (float*)d_out;

    void *p_f1t, *p_x, *p_y1, *p_y2, *p_sc1, *p_sh1, *p_sc2, *p_sh2;
    cudaGetSymbolAddress(&p_f1t, g_f1t);
    cudaGetSymbolAddress(&p_x,   g_x);
    cudaGetSymbolAddress(&p_y1,  g_y1);
    cudaGetSymbolAddress(&p_y2,  g_y2);
    cudaGetSymbolAddress(&p_sc1, g_scale1);
    cudaGetSymbolAddress(&p_sh1, g_shift1);
    cudaGetSymbolAddress(&p_sc2, g_scale2);
    cudaGetSymbolAddress(&p_sh2, g_shift2);

    cudaFuncSetAttribute(mma_gemm<CTOT, false>,
                         cudaFuncAttributeMaxDynamicSharedMemorySize, SM_TOT);
    cudaFuncSetAttribute(mma_gemm<HDIM, true>,
                         cudaFuncAttributeMaxDynamicSharedMemorySize, SM_TOT);

    dim3 tb(32, 8);

    transpose_f1<<<dim3(NPTS1 / 32, CH1 / 32, BATCH), tb>>>(features1, (float*)p_f1t);
    transpose_f2s<<<dim3(NPTS2 / 32, 6, BATCH), tb>>>(features2, skipf, (float*)p_x);
    knn_kernel<<<dim3(NPTS2 / 32, BATCH), 256>>>(points1, points2);
    interp_kernel<<<MROWS / 8, 256>>>();

    mma_gemm<CTOT, false><<<dim3(MROWS / 128, 2), 256, SM_TOT>>>(
        (const float*)p_x, W1, b1, nullptr, nullptr, (float*)p_y1);
    finalize_kernel<<<256, 256>>>(g1, be1, (float*)p_sc1, (float*)p_sh1);

    mma_gemm<HDIM, true><<<dim3(MROWS / 128, 2), 256, SM_TOT>>>(
        (const float*)p_y1, W2, b2,
        (const float*)p_sc1, (const float*)p_sh1, (float*)p_y2);
    finalize_kernel<<<256, 256>>>(g2, be2, (float*)p_sc2, (float*)p_sh2);

    output_kernel<<<dim3(NPTS2 / 32, HDIM / 32, BATCH), tb>>>(out);
}